// round 5
// baseline (speedup 1.0000x reference)
#include <cuda_runtime.h>
#include <cuda_bf16.h>
#include <cstdint>
#include <math.h>

#define NTOK 98304
#define EXP 6
#define TRAJ_LEN (NTOK*120)
#define SCORE_OFF TRAJ_LEN
#define AUX_OFF   (SCORE_OFF + NTOK)
#define PROBS_OFF (AUX_OFF + 1)

// ======================= helpers ===========================================
__device__ __forceinline__ uint32_t smem_u32(const void* p) {
    uint32_t a;
    asm("{ .reg .u64 t; cvta.to.shared.u64 t, %1; cvt.u32.u64 %0, t; }" : "=r"(a) : "l"(p));
    return a;
}
__device__ __forceinline__ uint32_t swz(uint32_t o) { return o ^ ((o >> 3) & 0x70); }

__device__ __forceinline__ void ldsm4(uint32_t* r, uint32_t addr) {
    asm volatile("ldmatrix.sync.aligned.m8n8.x4.shared.b16 {%0,%1,%2,%3}, [%4];"
        : "=r"(r[0]), "=r"(r[1]), "=r"(r[2]), "=r"(r[3]) : "r"(addr));
}
__device__ __forceinline__ void mma16816(float* d, const uint32_t* a, const uint32_t* b) {
    asm volatile("mma.sync.aligned.m16n8k16.row.col.f32.bf16.bf16.f32 "
        "{%0,%1,%2,%3}, {%4,%5,%6,%7}, {%8,%9}, {%0,%1,%2,%3};"
        : "+f"(d[0]), "+f"(d[1]), "+f"(d[2]), "+f"(d[3])
        : "r"(a[0]), "r"(a[1]), "r"(a[2]), "r"(a[3]), "r"(b[0]), "r"(b[1]));
}
__device__ __forceinline__ float gelu_exact(float x) {
    return 0.5f * x * (1.0f + erff(x * 0.7071067811865476f));
}
__device__ __forceinline__ uint32_t pack_bf2(__nv_bfloat16 a, __nv_bfloat16 b) {
    return (uint32_t)__bfloat16_as_ushort(a) | ((uint32_t)__bfloat16_as_ushort(b) << 16);
}

// ======================= scratch (device globals) ===========================
__device__ __nv_bfloat16 g_Xh[NTOK*128],  g_Xm[NTOK*128],  g_Xl[NTOK*128];
__device__ __nv_bfloat16 g_H1h[NTOK*256], g_H1m[NTOK*256], g_H1l[NTOK*256];
__device__ __nv_bfloat16 g_G1h[NTOK*256], g_G1l[NTOK*256];
__device__ __nv_bfloat16 g_G2h[NTOK*256], g_G2l[NTOK*256];
__device__ __nv_bfloat16 g_S1h[NTOK*128], g_S1l[NTOK*128];
__device__ __nv_bfloat16 g_wr1h[32768],  g_wr1m[32768],  g_wr1l[32768];
__device__ __nv_bfloat16 g_wr2h[32768],  g_wr2m[32768],  g_wr2l[32768];
__device__ __nv_bfloat16 g_wt1h[196608], g_wt1l[196608];
__device__ __nv_bfloat16 g_wt2h[393216], g_wt2l[393216];
__device__ __nv_bfloat16 g_wt3h[196608], g_wt3l[196608];
__device__ __nv_bfloat16 g_ws1h[98304],  g_ws1l[98304];
__device__ __nv_bfloat16 g_ws2h[49152],  g_ws2l[49152];
__device__ int   g_list[EXP*NTOK];
__device__ float g_wlist[EXP*NTOK];
__device__ int   g_cnt[8];
__device__ float g_partials[256*6];

// ======================= init + conversions ================================
__global__ void init_kernel(float* __restrict__ out) {
    long i = (long)blockIdx.x * blockDim.x + threadIdx.x;  // 11616*256 float4s
    ((float4*)out)[i] = make_float4(0.f, 0.f, 0.f, 0.f);   // traj + scores
    if (blockIdx.x == 0 && threadIdx.x < 8) g_cnt[threadIdx.x] = 0;
}

__global__ void convert_x(const float* __restrict__ x,
                          __nv_bfloat16* __restrict__ x0, __nv_bfloat16* __restrict__ x1,
                          __nv_bfloat16* __restrict__ x2) {
    long i = (long)blockIdx.x * 256 + threadIdx.x;
    float v = x[i];
    __nv_bfloat16 h = __float2bfloat16(v);
    float r = v - __bfloat162float(h);
    __nv_bfloat16 m = __float2bfloat16(r);
    x0[i] = h; x1[i] = m;
    x2[i] = __float2bfloat16(r - __bfloat162float(m));
}

// W [K,Nin] f32 row-major (expert stride) -> SW128-swizzled bf16 images.
// Per 64-k chunk: Npad rows (n) of 128 bytes (64 k-values) in 8-row atoms.
__global__ void convert_w(const float* __restrict__ W,
                          __nv_bfloat16* __restrict__ o0, __nv_bfloat16* __restrict__ o1,
                          __nv_bfloat16* __restrict__ o2,
                          int Nin, int Npad, long wstride, long ostride) {
    int e = blockIdx.z;
    int idx = blockIdx.x * 256 + threadIdx.x;
    int ce = Npad * 64;
    int c = idx / ce, rem = idx - c * ce;
    int n = rem >> 6, kk = rem & 63;
    float v = (n < Nin) ? W[(long)e * wstride + (long)(c * 64 + kk) * Nin + n] : 0.f;
    __nv_bfloat16 h = __float2bfloat16(v);
    float r = v - __bfloat162float(h);
    __nv_bfloat16 m = __float2bfloat16(r);
    uint32_t bo = (uint32_t)(n >> 3) * 1024u + (uint32_t)(n & 7) * 128u + (uint32_t)kk * 2u;
    bo = swz(bo);
    long o = (long)e * ostride + (long)c * ce + (bo >> 1);
    o0[o] = h; o1[o] = m;
    if (o2) o2[o] = __float2bfloat16(r - __bfloat162float(m));
}

// ======================= mma.sync split-bf16 GEMM ===========================
// CTA: 128 rows x 64-col n-slices, k chunks of 64. 8 warps 4(M)x2(N).
// EPI 0: bias+GELU -> split-bf16 (2/3 way) activation store
// EPI 1: router tail (bias+GELU, logits via w3, softmax/probs/top2/lists)
// EPI 3: traj scatter: outF[token*120+cc] += wgt*(v+bias[cc]), cc<120
// EPI 4: score: outF[token] += wgt*(dot(GELU(v+bias), w3)+b3)
template<int N, int K, int EPI, bool GATHER, bool T6>
__global__ void __launch_bounds__(256)
gemmW(const __nv_bfloat16* __restrict__ A0b, const __nv_bfloat16* __restrict__ A1b,
      const __nv_bfloat16* __restrict__ A2b,
      const __nv_bfloat16* __restrict__ B0b, const __nv_bfloat16* __restrict__ B1b,
      const __nv_bfloat16* __restrict__ B2b,
      const float* __restrict__ bias,
      const int* __restrict__ gather, const int* __restrict__ tokens,
      const float* __restrict__ wl,
      const int* __restrict__ cntPtr, int Mfixed,
      __nv_bfloat16* __restrict__ o0, __nv_bfloat16* __restrict__ o1,
      __nv_bfloat16* __restrict__ o2,
      float* __restrict__ outF,
      int* __restrict__ lists, float* __restrict__ wlists, int* __restrict__ cnts,
      const float* __restrict__ w3, const float* __restrict__ b3)
{
    constexpr int NA = T6 ? 3 : 2;
    constexpr int NT = T6 ? 6 : 3;
    constexpr int NC = K / 64;
    constexpr int NSL = N / 64;
    constexpr int A_BYTES = 16384, B_BYTES = 8192;
    constexpr int B_OFF = NA * A_BYTES;
    constexpr int C_OFF = NA * (A_BYTES + B_BYTES);
    constexpr int CP = 65;
    constexpr int SW_OFF = C_OFF + 128 * CP * 4;
    constexpr int BC_OFF = SW_OFF + 3072;

    extern __shared__ char smem[];
    int Mrows = cntPtr ? *cntPtr : Mfixed;
    int rowBase = blockIdx.x << 7;
    if (rowBase >= Mrows) return;
    const int t = threadIdx.x, lane = t & 31, w = t >> 5;
    const int wm = w & 3, wn = w >> 2;
    uint32_t sb = smem_u32(smem);
    float* Csm  = (float*)(smem + C_OFF);
    float* sw   = (float*)(smem + SW_OFF);
    int* bcnt   = (int*)(smem + BC_OFF);
    int* bbase  = bcnt + 8;

    if (EPI == 1) { for (int i = t; i < 768; i += 256) sw[i] = w3[i]; if (t < 8) bcnt[t] = 0; }
    if (EPI == 4 && t < 64) sw[t] = w3[t];

    const __nv_bfloat16* Asrc[3] = {A0b, A1b, A2b};
    const uint4* Bsrc[3] = {(const uint4*)B0b, (const uint4*)B1b, (const uint4*)B2b};

    // ldmatrix lane addressing
    uint32_t a_rowoff[2];
#pragma unroll
    for (int mt = 0; mt < 2; mt++) {
        int r = wm * 32 + mt * 16 + (lane & 15);
        a_rowoff[mt] = (uint32_t)((r >> 3) * 1024 + (r & 7) * 128);
    }
    const uint32_t a_klane = (uint32_t)((lane >> 4) * 16);
    uint32_t b_rowoff[2];
#pragma unroll
    for (int p = 0; p < 2; p++) {
        int r = wn * 32 + p * 16 + ((lane >> 4) & 1) * 8 + (lane & 7);
        b_rowoff[p] = (uint32_t)((r >> 3) * 1024 + (r & 7) * 128);
    }
    const uint32_t b_klane = (uint32_t)(((lane >> 3) & 1) * 16);

    float lg[6] = {0.f, 0.f, 0.f, 0.f, 0.f, 0.f};

    for (int ns = 0; ns < NSL; ns++) {
        float acc[2][4][4];
#pragma unroll
        for (int mt = 0; mt < 2; mt++)
#pragma unroll
            for (int nt = 0; nt < 4; nt++)
#pragma unroll
                for (int q = 0; q < 4; q++) acc[mt][nt][q] = 0.f;

        for (int c = 0; c < NC; c++) {
            __syncthreads();
            // stage A (128 rows x 64 k, per split)
#pragma unroll
            for (int a = 0; a < NA; a++) {
                const __nv_bfloat16* Ab = Asrc[a];
                for (int i = t; i < 1024; i += 256) {
                    int row = i >> 3, seg = i & 7;
                    int gr = rowBase + row;
                    long sr = 0;
                    if (gr < Mrows) sr = GATHER ? (long)gather[gr] : (long)gr;
                    uint4 v = *(const uint4*)(Ab + sr * K + c * 64 + seg * 8);
                    *(uint4*)(smem + a * A_BYTES +
                        swz((uint32_t)((row >> 3) * 1024 + (row & 7) * 128 + seg * 16))) = v;
                }
            }
            // stage B (contiguous, already swizzled)
#pragma unroll
            for (int a = 0; a < NA; a++) {
                const uint4* src = Bsrc[a] + (long)c * (N * 8) + ns * 512;
                uint4* dst = (uint4*)(smem + B_OFF + a * B_BYTES);
                for (int i = t; i < 512; i += 256) dst[i] = src[i];
            }
            __syncthreads();
            // compute 4 k-steps of 16
#pragma unroll
            for (int ks = 0; ks < 4; ks++) {
                uint32_t af[NA][2][4], bf[NA][2][4];
#pragma unroll
                for (int a = 0; a < NA; a++) {
#pragma unroll
                    for (int mt = 0; mt < 2; mt++)
                        ldsm4(af[a][mt], sb + a * A_BYTES +
                              swz(a_rowoff[mt] + (uint32_t)ks * 32 + a_klane));
#pragma unroll
                    for (int p = 0; p < 2; p++)
                        ldsm4(bf[a][p], sb + B_OFF + a * B_BYTES +
                              swz(b_rowoff[p] + (uint32_t)ks * 32 + b_klane));
                }
                const int TI[6] = {0, 0, 1, 1, 0, 2}, TJ[6] = {0, 1, 0, 1, 2, 0};
#pragma unroll
                for (int tt = 0; tt < NT; tt++)
#pragma unroll
                    for (int mt = 0; mt < 2; mt++)
#pragma unroll
                        for (int nt = 0; nt < 4; nt++)
                            mma16816(acc[mt][nt], af[TI[tt]][mt],
                                     &bf[TJ[tt]][nt >> 1][(nt & 1) * 2]);
            }
        }
        // store fragments to smem C tile
        __syncthreads();
        {
            int r0 = wm * 32 + (lane >> 2);
            int cb = wn * 32 + (lane & 3) * 2;
#pragma unroll
            for (int mt = 0; mt < 2; mt++)
#pragma unroll
                for (int nt = 0; nt < 4; nt++) {
                    float* p = Csm + (r0 + mt * 16) * CP + cb + nt * 8;
                    p[0] = acc[mt][nt][0]; p[1] = acc[mt][nt][1];
                    p += 8 * CP;
                    p[0] = acc[mt][nt][2]; p[1] = acc[mt][nt][3];
                }
        }
        __syncthreads();
        // row-wise epilogue (threads 0..127, thread t = local row t)
        if (t < 128) {
            int row = rowBase + t;
            bool act = row < Mrows;
            if (EPI == 0) {
                if (act) {
                    uint32_t p0[32], p1[32], p2[32];
#pragma unroll
                    for (int j = 0; j < 32; j++) {
                        float v0 = gelu_exact(Csm[t*CP + 2*j]     + bias[ns*64 + 2*j]);
                        float v1 = gelu_exact(Csm[t*CP + 2*j + 1] + bias[ns*64 + 2*j + 1]);
                        __nv_bfloat16 h0 = __float2bfloat16(v0), h1 = __float2bfloat16(v1);
                        float r0 = v0 - __bfloat162float(h0), r1 = v1 - __bfloat162float(h1);
                        __nv_bfloat16 m0 = __float2bfloat16(r0), m1 = __float2bfloat16(r1);
                        p0[j] = pack_bf2(h0, h1);
                        p1[j] = pack_bf2(m0, m1);
                        if (T6) {
                            __nv_bfloat16 l0 = __float2bfloat16(r0 - __bfloat162float(m0));
                            __nv_bfloat16 l1 = __float2bfloat16(r1 - __bfloat162float(m1));
                            p2[j] = pack_bf2(l0, l1);
                        }
                    }
                    long rb = (long)row * N + ns * 64;
                    uint4* q0 = (uint4*)(o0 + rb);
                    uint4* q1 = (uint4*)(o1 + rb);
#pragma unroll
                    for (int q = 0; q < 8; q++) {
                        q0[q] = make_uint4(p0[4*q], p0[4*q+1], p0[4*q+2], p0[4*q+3]);
                        q1[q] = make_uint4(p1[4*q], p1[4*q+1], p1[4*q+2], p1[4*q+3]);
                    }
                    if (T6) {
                        uint4* q2 = (uint4*)(o2 + rb);
#pragma unroll
                        for (int q = 0; q < 8; q++)
                            q2[q] = make_uint4(p2[4*q], p2[4*q+1], p2[4*q+2], p2[4*q+3]);
                    }
                }
            } else if (EPI == 1) {
                if (act) {
#pragma unroll
                    for (int j = 0; j < 64; j++) {
                        int cc = ns * 64 + j;
                        float h = gelu_exact(Csm[t*CP + j] + bias[cc]);
#pragma unroll
                        for (int e = 0; e < 6; e++) lg[e] += h * sw[cc * 6 + e];
                    }
                }
            } else if (EPI == 3) {
                if (act) {
                    int tok = tokens[row];
                    float wgt = wl[row];
#pragma unroll
                    for (int j = 0; j < 64; j++) {
                        int cc = ns * 64 + j;
                        if (cc < 120) {
                            float v = Csm[t*CP + j] + bias[cc];
                            float* p = outF + (long)tok * 120 + cc;
                            *p += wgt * v;   // unique (token,cc) per launch; launches serialized
                        }
                    }
                }
            } else if (EPI == 4) {
                if (act) {
                    int tok = tokens[row];
                    float wgt = wl[row];
                    float s = 0.f;
#pragma unroll
                    for (int j = 0; j < 64; j++)
                        s += gelu_exact(Csm[t*CP + j] + bias[j]) * sw[j];
                    outF[tok] += wgt * (s + b3[0]);
                }
            }
        }
    }

    // router tail: softmax/probs, top-2, block-aggregated list build
    if (EPI == 1) {
        int row = rowBase + t;
        bool act = (t < 128) && (row < Mrows);
        int i0 = 0, i1 = 1, pos0 = 0, pos1 = 0; float w0 = 0.f, w1 = 0.f;
        __syncthreads();
        if (act) {
#pragma unroll
            for (int e = 0; e < 6; e++) lg[e] += b3[e];
            float mx = lg[0];
#pragma unroll
            for (int e = 1; e < 6; e++) mx = fmaxf(mx, lg[e]);
            float p[6], s = 0.f;
#pragma unroll
            for (int e = 0; e < 6; e++) { p[e] = expf(lg[e] - mx); s += p[e]; }
            float inv = 1.f / s;
            float* pr = outF + (long)row * 6;
#pragma unroll
            for (int e = 0; e < 6; e++) pr[e] = p[e] * inv;
            i0 = 0;
#pragma unroll
            for (int e = 1; e < 6; e++) if (lg[e] > lg[i0]) i0 = e;
            i1 = (i0 == 0) ? 1 : 0;
#pragma unroll
            for (int e = 0; e < 6; e++) if (e != i0 && lg[e] > lg[i1]) i1 = e;
            float rr = expf(lg[i1] - lg[i0]);
            w0 = 1.f / (1.f + rr); w1 = rr * w0;
            pos0 = atomicAdd(&bcnt[i0], 1);
            pos1 = atomicAdd(&bcnt[i1], 1);
        }
        __syncthreads();
        if (t < 6) bbase[t] = atomicAdd(&cnts[t], bcnt[t]);
        __syncthreads();
        if (act) {
            int s0 = bbase[i0] + pos0, s1 = bbase[i1] + pos1;
            lists[i0 * NTOK + s0] = row;  wlists[i0 * NTOK + s0] = w0;
            lists[i1 * NTOK + s1] = row;  wlists[i1 * NTOK + s1] = w1;
        }
    }
}

// ---------------- aux loss (deterministic 2-stage tree reduction) ----------
__global__ __launch_bounds__(256) void aux_partial(const float* __restrict__ probs,
                                                   float* __restrict__ partials) {
    __shared__ float s[256][6];
    float acc[6] = {0.f, 0.f, 0.f, 0.f, 0.f, 0.f};
    int base = blockIdx.x * 384;
    for (int it = threadIdx.x; it < 384; it += 256) {
        const float* p = probs + (long)(base + it) * 6;
#pragma unroll
        for (int e = 0; e < 6; e++) acc[e] += p[e];
    }
#pragma unroll
    for (int e = 0; e < 6; e++) s[threadIdx.x][e] = acc[e];
    __syncthreads();
    for (int off = 128; off; off >>= 1) {
        if (threadIdx.x < off)
#pragma unroll
            for (int e = 0; e < 6; e++) s[threadIdx.x][e] += s[threadIdx.x + off][e];
        __syncthreads();
    }
    if (threadIdx.x < 6) partials[blockIdx.x * 6 + threadIdx.x] = s[0][threadIdx.x];
}

__global__ __launch_bounds__(256) void aux_final(const float* __restrict__ partials,
                                                 float* __restrict__ out_aux) {
    __shared__ float s[256][6];
#pragma unroll
    for (int e = 0; e < 6; e++) s[threadIdx.x][e] = partials[threadIdx.x * 6 + e];
    __syncthreads();
    for (int off = 128; off; off >>= 1) {
        if (threadIdx.x < off)
#pragma unroll
            for (int e = 0; e < 6; e++) s[threadIdx.x][e] += s[threadIdx.x + off][e];
        __syncthreads();
    }
    if (threadIdx.x == 0) {
        float aux = 0.f;
#pragma unroll
        for (int e = 0; e < 6; e++) {
            float avg = s[0][e] / (float)NTOK;
            aux += avg * avg;
        }
        out_aux[0] = 6.f * aux;
    }
}

// ---------------------------- host launcher --------------------------------
extern "C" void kernel_launch(void* const* d_in, const int* in_sizes, int n_in,
                              void* d_out, int out_size)
{
    const float* x   = (const float*)d_in[0];
    const float* rW1 = (const float*)d_in[1];  const float* rb1 = (const float*)d_in[2];
    const float* rW2 = (const float*)d_in[3];  const float* rb2 = (const float*)d_in[4];
    const float* rW3 = (const float*)d_in[5];  const float* rb3 = (const float*)d_in[6];
    const float* tW1 = (const float*)d_in[7];  const float* tb1 = (const float*)d_in[8];
    const float* tW2 = (const float*)d_in[9];  const float* tb2 = (const float*)d_in[10];
    const float* tW3 = (const float*)d_in[11]; const float* tb3 = (const float*)d_in[12];
    const float* sW1 = (const float*)d_in[13]; const float* sb1 = (const float*)d_in[14];
    const float* sW2 = (const float*)d_in[15]; const float* sb2 = (const float*)d_in[16];
    const float* sW3 = (const float*)d_in[17]; const float* sb3 = (const float*)d_in[18];
    float* out = (float*)d_out;

    __nv_bfloat16 *Xh,*Xm,*Xl,*H1h,*H1m,*H1l,*G1h,*G1l,*G2h,*G2l,*S1h,*S1l;
    __nv_bfloat16 *wr1h,*wr1m,*wr1l,*wr2h,*wr2m,*wr2l;
    __nv_bfloat16 *wt1h,*wt1l,*wt2h,*wt2l,*wt3h,*wt3l,*ws1h,*ws1l,*ws2h,*ws2l;
    int *list, *cnt; float *wlist, *partials;
    cudaGetSymbolAddress((void**)&Xh, g_Xh);   cudaGetSymbolAddress((void**)&Xm, g_Xm);
    cudaGetSymbolAddress((void**)&Xl, g_Xl);
    cudaGetSymbolAddress((void**)&H1h, g_H1h); cudaGetSymbolAddress((void**)&H1m, g_H1m);
    cudaGetSymbolAddress((void**)&H1l, g_H1l);
    cudaGetSymbolAddress((void**)&G1h, g_G1h); cudaGetSymbolAddress((void**)&G1l, g_G1l);
    cudaGetSymbolAddress((void**)&G2h, g_G2h); cudaGetSymbolAddress((void**)&G2l, g_G2l);
    cudaGetSymbolAddress((void**)&S1h, g_S1h); cudaGetSymbolAddress((void**)&S1l, g_S1l);
    cudaGetSymbolAddress((void**)&wr1h, g_wr1h); cudaGetSymbolAddress((void**)&wr1m, g_wr1m);
    cudaGetSymbolAddress((void**)&wr1l, g_wr1l);
    cudaGetSymbolAddress((void**)&wr2h, g_wr2h); cudaGetSymbolAddress((void**)&wr2m, g_wr2m);
    cudaGetSymbolAddress((void**)&wr2l, g_wr2l);
    cudaGetSymbolAddress((void**)&wt1h, g_wt1h); cudaGetSymbolAddress((void**)&wt1l, g_wt1l);
    cudaGetSymbolAddress((void**)&wt2h, g_wt2h); cudaGetSymbolAddress((void**)&wt2l, g_wt2l);
    cudaGetSymbolAddress((void**)&wt3h, g_wt3h); cudaGetSymbolAddress((void**)&wt3l, g_wt3l);
    cudaGetSymbolAddress((void**)&ws1h, g_ws1h); cudaGetSymbolAddress((void**)&ws1l, g_ws1l);
    cudaGetSymbolAddress((void**)&ws2h, g_ws2h); cudaGetSymbolAddress((void**)&ws2l, g_ws2l);
    cudaGetSymbolAddress((void**)&list, g_list); cudaGetSymbolAddress((void**)&wlist, g_wlist);
    cudaGetSymbolAddress((void**)&cnt, g_cnt);   cudaGetSymbolAddress((void**)&partials, g_partials);

    // smem: NA*(16K+8K) + C(128*65*4=33280) + sw(3072) + counters(64)
    const int S_NA2 = 2*24576 + 33280 + 3072 + 64;   // 85568
    const int S_NA3 = 3*24576 + 33280 + 3072 + 64;   // 110144
    cudaFuncSetAttribute(gemmW<256,128,0,false,true>,  cudaFuncAttributeMaxDynamicSharedMemorySize, S_NA3);
    cudaFuncSetAttribute(gemmW<128,256,1,false,true>,  cudaFuncAttributeMaxDynamicSharedMemorySize, S_NA3);
    cudaFuncSetAttribute(gemmW<256,128,0,true,false>,  cudaFuncAttributeMaxDynamicSharedMemorySize, S_NA2);
    cudaFuncSetAttribute(gemmW<256,256,0,false,false>, cudaFuncAttributeMaxDynamicSharedMemorySize, S_NA2);
    cudaFuncSetAttribute(gemmW<128,256,3,false,false>, cudaFuncAttributeMaxDynamicSharedMemorySize, S_NA2);
    cudaFuncSetAttribute(gemmW<128,128,0,true,false>,  cudaFuncAttributeMaxDynamicSharedMemorySize, S_NA2);
    cudaFuncSetAttribute(gemmW<64,128,4,false,false>,  cudaFuncAttributeMaxDynamicSharedMemorySize, S_NA2);

    // 1. zero traj+scores + counters; split inputs; build weight images
    init_kernel<<<11616, 256>>>(out);
    convert_x<<<NTOK*128/256, 256>>>(x, Xh, Xm, Xl);
    convert_w<<<dim3(128,1,1), 256>>>(rW1, wr1h, wr1m, wr1l, 256, 256, 0, 0);
    convert_w<<<dim3(128,1,1), 256>>>(rW2, wr2h, wr2m, wr2l, 128, 128, 0, 0);
    convert_w<<<dim3(128,1,6), 256>>>(tW1, wt1h, wt1l, nullptr, 256, 256, 128L*256, 32768);
    convert_w<<<dim3(256,1,6), 256>>>(tW2, wt2h, wt2l, nullptr, 256, 256, 256L*256, 65536);
    convert_w<<<dim3(128,1,6), 256>>>(tW3, wt3h, wt3l, nullptr, 120, 128, 256L*120, 32768);
    convert_w<<<dim3(64,1,6),  256>>>(sW1, ws1h, ws1l, nullptr, 128, 128, 128L*128, 16384);
    convert_w<<<dim3(32,1,6),  256>>>(sW2, ws2h, ws2l, nullptr, 64,  64,  128L*64,  8192);

    const int GB = NTOK / 128;  // 768

    // 2. router (3-split / 6-term for selection accuracy)
    gemmW<256,128,0,false,true><<<GB,256,S_NA3>>>(Xh,Xm,Xl, wr1h,wr1m,wr1l, rb1,
        nullptr,nullptr,nullptr, nullptr, NTOK, H1h,H1m,H1l,
        nullptr, nullptr,nullptr,nullptr, nullptr,nullptr);
    gemmW<128,256,1,false,true><<<GB,256,S_NA3>>>(H1h,H1m,H1l, wr2h,wr2m,wr2l, rb2,
        nullptr,nullptr,nullptr, nullptr, NTOK, nullptr,nullptr,nullptr,
        out + PROBS_OFF, list, wlist, cnt, rW3, rb3);

    // 3. per-expert top-2 compute (dynamic counts read on device)
    for (int e = 0; e < EXP; e++) {
        const int* lst = list + e * NTOK;
        const float* wle = wlist + e * NTOK;
        const int* cp = cnt + e;
        gemmW<256,128,0,true,false><<<GB,256,S_NA2>>>(Xh,Xm,nullptr,
            wt1h + e*32768L, wt1l + e*32768L, nullptr, tb1 + e*256,
            lst, nullptr, nullptr, cp, 0, G1h,G1l,nullptr,
            nullptr, nullptr,nullptr,nullptr, nullptr,nullptr);
        gemmW<256,256,0,false,false><<<GB,256,S_NA2>>>(G1h,G1l,nullptr,
            wt2h + e*65536L, wt2l + e*65536L, nullptr, tb2 + e*256,
            nullptr, nullptr, nullptr, cp, 0, G2h,G2l,nullptr,
            nullptr, nullptr,nullptr,nullptr, nullptr,nullptr);
        gemmW<128,256,3,false,false><<<GB,256,S_NA2>>>(G2h,G2l,nullptr,
            wt3h + e*32768L, wt3l + e*32768L, nullptr, tb3 + e*120,
            nullptr, lst, wle, cp, 0, nullptr,nullptr,nullptr,
            out, nullptr,nullptr,nullptr, nullptr,nullptr);
        gemmW<128,128,0,true,false><<<GB,256,S_NA2>>>(Xh,Xm,nullptr,
            ws1h + e*16384L, ws1l + e*16384L, nullptr, sb1 + e*128,
            lst, nullptr, nullptr, cp, 0, S1h,S1l,nullptr,
            nullptr, nullptr,nullptr,nullptr, nullptr,nullptr);
        gemmW<64,128,4,false,false><<<GB,256,S_NA2>>>(S1h,S1l,nullptr,
            ws2h + e*8192L, ws2l + e*8192L, nullptr, sb2 + e*64,
            nullptr, lst, wle, cp, 0, nullptr,nullptr,nullptr,
            out + SCORE_OFF, nullptr,nullptr,nullptr, sW3 + e*64, sb3 + e);
    }

    // 4. aux loss from probs
    aux_partial<<<256, 256>>>(out + PROBS_OFF, partials);
    aux_final<<<1, 256>>>(partials, out + AUX_OFF);
}

// round 6
// speedup vs baseline: 2.1800x; 2.1800x over previous
#include <cuda_runtime.h>
#include <cuda_bf16.h>
#include <cstdint>
#include <math.h>

#define NTOK 98304
#define EXP 6
#define TRAJ_LEN (NTOK*120)
#define SCORE_OFF TRAJ_LEN
#define AUX_OFF   (SCORE_OFF + NTOK)
#define PROBS_OFF (AUX_OFF + 1)

// ======================= helpers ===========================================
__device__ __forceinline__ uint32_t smem_u32(const void* p) {
    uint32_t a;
    asm("{ .reg .u64 t; cvta.to.shared.u64 t, %1; cvt.u32.u64 %0, t; }" : "=r"(a) : "l"(p));
    return a;
}
__device__ __forceinline__ uint32_t swz(uint32_t o) { return o ^ ((o >> 3) & 0x70); }

__device__ __forceinline__ void ldsm4(uint32_t* r, uint32_t addr) {
    asm volatile("ldmatrix.sync.aligned.m8n8.x4.shared.b16 {%0,%1,%2,%3}, [%4];"
        : "=r"(r[0]), "=r"(r[1]), "=r"(r[2]), "=r"(r[3]) : "r"(addr));
}
__device__ __forceinline__ void mma16816(float* d, const uint32_t* a, const uint32_t* b) {
    asm volatile("mma.sync.aligned.m16n8k16.row.col.f32.bf16.bf16.f32 "
        "{%0,%1,%2,%3}, {%4,%5,%6,%7}, {%8,%9}, {%0,%1,%2,%3};"
        : "+f"(d[0]), "+f"(d[1]), "+f"(d[2]), "+f"(d[3])
        : "r"(a[0]), "r"(a[1]), "r"(a[2]), "r"(a[3]), "r"(b[0]), "r"(b[1]));
}
#define CP_ASYNC16(dst, src, sz) \
    asm volatile("cp.async.cg.shared.global [%0], [%1], 16, %2;" \
        :: "r"(dst), "l"(src), "r"(sz))
#define CP_COMMIT() asm volatile("cp.async.commit_group;")
#define CP_WAIT1()  asm volatile("cp.async.wait_group 1;")
#define CP_WAIT0()  asm volatile("cp.async.wait_group 0;")

__device__ __forceinline__ float gelu_exact(float x) {
    return 0.5f * x * (1.0f + erff(x * 0.7071067811865476f));
}
__device__ __forceinline__ uint32_t pack_bf2(__nv_bfloat16 a, __nv_bfloat16 b) {
    return (uint32_t)__bfloat16_as_ushort(a) | ((uint32_t)__bfloat16_as_ushort(b) << 16);
}

// ======================= scratch (device globals) ===========================
__device__ __nv_bfloat16 g_Xh[NTOK*128],  g_Xm[NTOK*128],  g_Xl[NTOK*128];
__device__ __nv_bfloat16 g_H1h[NTOK*256], g_H1m[NTOK*256], g_H1l[NTOK*256];
__device__ __nv_bfloat16 g_G1h[NTOK*256], g_G1l[NTOK*256];
__device__ __nv_bfloat16 g_G2h[NTOK*256], g_G2l[NTOK*256];
__device__ __nv_bfloat16 g_S1h[NTOK*128], g_S1l[NTOK*128];
__device__ __nv_bfloat16 g_wr1h[32768],  g_wr1m[32768],  g_wr1l[32768];
__device__ __nv_bfloat16 g_wr2h[32768],  g_wr2m[32768],  g_wr2l[32768];
__device__ __nv_bfloat16 g_wt1h[196608], g_wt1l[196608];
__device__ __nv_bfloat16 g_wt2h[393216], g_wt2l[393216];
__device__ __nv_bfloat16 g_wt3h[196608], g_wt3l[196608];
__device__ __nv_bfloat16 g_ws1h[98304],  g_ws1l[98304];
__device__ __nv_bfloat16 g_ws2h[49152],  g_ws2l[49152];
__device__ int   g_list[EXP*NTOK];
__device__ float g_wlist[EXP*NTOK];
__device__ int   g_cnt[8];
__device__ float g_partials[256*6];

// ======================= init + conversions ================================
__global__ void init_kernel(float* __restrict__ out) {
    long i = (long)blockIdx.x * blockDim.x + threadIdx.x;
    ((float4*)out)[i] = make_float4(0.f, 0.f, 0.f, 0.f);   // traj + scores
    if (blockIdx.x == 0 && threadIdx.x < 8) g_cnt[threadIdx.x] = 0;
}

__global__ void convert_x(const float* __restrict__ x,
                          __nv_bfloat16* __restrict__ x0, __nv_bfloat16* __restrict__ x1,
                          __nv_bfloat16* __restrict__ x2) {
    long i = (long)blockIdx.x * 256 + threadIdx.x;
    float v = x[i];
    __nv_bfloat16 h = __float2bfloat16(v);
    float r = v - __bfloat162float(h);
    __nv_bfloat16 m = __float2bfloat16(r);
    x0[i] = h; x1[i] = m;
    x2[i] = __float2bfloat16(r - __bfloat162float(m));
}

// W [K,Nin] f32 row-major (expert stride) -> SW128-swizzled bf16 images.
__global__ void convert_w(const float* __restrict__ W,
                          __nv_bfloat16* __restrict__ o0, __nv_bfloat16* __restrict__ o1,
                          __nv_bfloat16* __restrict__ o2,
                          int Nin, int Npad, long wstride, long ostride) {
    int e = blockIdx.z;
    int idx = blockIdx.x * 256 + threadIdx.x;
    int ce = Npad * 64;
    int c = idx / ce, rem = idx - c * ce;
    int n = rem >> 6, kk = rem & 63;
    float v = (n < Nin) ? W[(long)e * wstride + (long)(c * 64 + kk) * Nin + n] : 0.f;
    __nv_bfloat16 h = __float2bfloat16(v);
    float r = v - __bfloat162float(h);
    __nv_bfloat16 m = __float2bfloat16(r);
    uint32_t bo = (uint32_t)(n >> 3) * 1024u + (uint32_t)(n & 7) * 128u + (uint32_t)kk * 2u;
    bo = swz(bo);
    long o = (long)e * ostride + (long)c * ce + (bo >> 1);
    o0[o] = h; o1[o] = m;
    if (o2) o2[o] = __float2bfloat16(r - __bfloat162float(m));
}

// ======================= pipelined mma.sync split-bf16 GEMM =================
// CTA: 128 rows x NTILE cols (grid.y slices 128-col blocks of N).
// k chunks of 64, 2-stage cp.async double buffer. 8 warps 4(M)x2(N).
// EPI 0: bias+GELU -> split-bf16 store (direct from fragments)
// EPI 1: router tail (logits via w3, softmax/probs/top2/lists)
// EPI 3: traj scatter: outF[token*120+cc] += wgt*(v+bias[cc]), cc<120
// EPI 4: score: outF[token] += wgt*(dot(GELU(v+bias), w3)+b3)
template<int NTILE, int K, int EPI, bool GATHER, bool T6>
__global__ void __launch_bounds__(256)
gemmW(const __nv_bfloat16* __restrict__ A0b, const __nv_bfloat16* __restrict__ A1b,
      const __nv_bfloat16* __restrict__ A2b,
      const __nv_bfloat16* __restrict__ B0b, const __nv_bfloat16* __restrict__ B1b,
      const __nv_bfloat16* __restrict__ B2b,
      const float* __restrict__ bias,
      const int* __restrict__ gather, const int* __restrict__ tokens,
      const float* __restrict__ wl,
      const int* __restrict__ cntPtr, int Mfixed,
      __nv_bfloat16* __restrict__ o0, __nv_bfloat16* __restrict__ o1,
      __nv_bfloat16* __restrict__ o2,
      int ldN, int npad4,
      float* __restrict__ outF,
      int* __restrict__ lists, float* __restrict__ wlists, int* __restrict__ cnts,
      const float* __restrict__ w3, const float* __restrict__ b3)
{
    constexpr int NA = T6 ? 3 : 2;
    constexpr int NT = T6 ? 6 : 3;
    constexpr int NC = K / 64;
    constexpr int NNT = NTILE / 16;        // n8 tiles per warp
    constexpr int NG  = NNT / 2;           // n16 ldmatrix groups per warp
    constexpr int ABYTES = 16384;
    constexpr int BBYTES = NTILE * 128;
    constexpr int STAGE  = NA * (ABYTES + BBYTES);
    constexpr int EXTRA  = 2 * STAGE;
    constexpr int NB4 = NTILE * 8;          // uint4 per B split chunk

    extern __shared__ char smem[];
    int Mrows = cntPtr ? *cntPtr : Mfixed;
    int rowBase = blockIdx.x << 7;
    if (rowBase >= Mrows) return;
    const int t = threadIdx.x, lane = t & 31, w = t >> 5;
    const int wm = w & 3, wn = w >> 2;
    uint32_t sb = smem_u32(smem);
    int*   sgat = (int*)(smem + EXTRA);
    float* sw   = (float*)(smem + EXTRA + 512);
    float* lgsm = (float*)(smem + EXTRA + 512 + 3072);
    int*   bcnt = (int*)(smem + EXTRA + 512 + 3072 + 3072);
    int*   bbase = bcnt + 8;

    if (GATHER && t < 128) { int gr = rowBase + t; sgat[t] = (gr < Mrows) ? gather[gr] : 0; }
    if (EPI == 1) {
        for (int i = t; i < 768; i += 256) { sw[i] = w3[i]; lgsm[i] = 0.f; }
        if (t < 8) bcnt[t] = 0;
    }
    if (EPI == 4) { if (t < 64) sw[t] = w3[t]; if (t < 128) lgsm[t] = 0.f; }
    __syncthreads();

    const __nv_bfloat16* Asp[3] = {A0b, A1b, A2b};
    const uint4* Bsp[3] = {(const uint4*)B0b, (const uint4*)B1b, (const uint4*)B2b};
    const int ny4 = blockIdx.y * 1024;   // col-slice offset into B chunk (128 rows * 8 uint4)

    // ldmatrix lane addressing (verified in R5)
    uint32_t aoff[2];
#pragma unroll
    for (int mt = 0; mt < 2; mt++) {
        int r = wm * 32 + mt * 16 + (lane & 15);
        aoff[mt] = (uint32_t)((r >> 3) * 1024 + (r & 7) * 128) + (uint32_t)((lane >> 4) * 16);
    }
    uint32_t boff[NG];
#pragma unroll
    for (int g = 0; g < NG; g++) {
        int r = wn * (NTILE / 2) + g * 16 + ((lane >> 4) & 1) * 8 + (lane & 7);
        boff[g] = (uint32_t)((r >> 3) * 1024 + (r & 7) * 128) + (uint32_t)(((lane >> 3) & 1) * 16);
    }

    // -------- staging (cp.async) --------
    auto stage = [&](int c, int s) {
        uint32_t base = sb + s * STAGE;
#pragma unroll
        for (int a = 0; a < NA; a++) {
            const __nv_bfloat16* Ab = Asp[a];
#pragma unroll
            for (int rep = 0; rep < 4; rep++) {
                int i = t + rep * 256;
                int row = i >> 3, seg = i & 7;
                int gr = rowBase + row;
                int val = (gr < Mrows) ? 16 : 0;
                long srw = GATHER ? (long)sgat[row] : (long)gr;
                const void* src = Ab + srw * (long)K + c * 64 + seg * 8;
                uint32_t dst = base + a * ABYTES +
                    swz((uint32_t)((row >> 3) * 1024 + (row & 7) * 128 + seg * 16));
                CP_ASYNC16(dst, src, val);
            }
        }
#pragma unroll
        for (int a = 0; a < NA; a++) {
            const uint4* src0 = Bsp[a] + (long)c * npad4 + ny4;
#pragma unroll
            for (int rep = 0; rep < NB4 / 256; rep++) {
                int i = t + rep * 256;
                CP_ASYNC16(base + NA * ABYTES + a * BBYTES + (uint32_t)i * 16, src0 + i, 16);
            }
        }
        CP_COMMIT();
    };

    float acc[2][NNT][4];
#pragma unroll
    for (int mt = 0; mt < 2; mt++)
#pragma unroll
        for (int nt = 0; nt < NNT; nt++)
#pragma unroll
            for (int q = 0; q < 4; q++) acc[mt][nt][q] = 0.f;

    stage(0, 0);
    for (int c = 0; c < NC; c++) {
        int s = c & 1;
        if (c + 1 < NC) { stage(c + 1, (c + 1) & 1); CP_WAIT1(); }
        else            { CP_WAIT0(); }
        __syncthreads();
        uint32_t base = sb + s * STAGE;
        const int TI[6] = {0, 0, 1, 1, 0, 2}, TJ[6] = {0, 1, 0, 1, 2, 0};
#pragma unroll
        for (int ks = 0; ks < 4; ks++) {
            uint32_t af[NA][2][4];
#pragma unroll
            for (int a = 0; a < NA; a++)
#pragma unroll
                for (int mt = 0; mt < 2; mt++)
                    ldsm4(af[a][mt], base + a * ABYTES + swz(aoff[mt] + (uint32_t)ks * 32));
#pragma unroll
            for (int g = 0; g < NG; g++) {
                uint32_t bf[NA][4];
#pragma unroll
                for (int a = 0; a < NA; a++)
                    ldsm4(bf[a], base + NA * ABYTES + a * BBYTES + swz(boff[g] + (uint32_t)ks * 32));
#pragma unroll
                for (int tt = 0; tt < NT; tt++)
#pragma unroll
                    for (int mt = 0; mt < 2; mt++)
#pragma unroll
                        for (int hn = 0; hn < 2; hn++)
                            mma16816(acc[mt][g * 2 + hn], af[TI[tt]][mt], &bf[TJ[tt]][hn * 2]);
            }
        }
        __syncthreads();
    }

    // ----------------------- epilogue (from fragments) ---------------------
    const int colW = wn * (NTILE / 2);
    const int colBase = blockIdx.y * NTILE;
#pragma unroll
    for (int mt = 0; mt < 2; mt++) {
#pragma unroll
        for (int h8 = 0; h8 < 2; h8++) {
            int rl = wm * 32 + mt * 16 + (lane >> 2) + h8 * 8;
            int row = rowBase + rl;
            bool act = row < Mrows;
            if (EPI == 0) {
                if (act) {
#pragma unroll
                    for (int nt = 0; nt < NNT; nt++) {
                        int gc = colBase + colW + nt * 8 + (lane & 3) * 2;
                        float v0 = gelu_exact(acc[mt][nt][h8 * 2 + 0] + __ldg(&bias[gc]));
                        float v1 = gelu_exact(acc[mt][nt][h8 * 2 + 1] + __ldg(&bias[gc + 1]));
                        __nv_bfloat16 b0 = __float2bfloat16(v0), b1 = __float2bfloat16(v1);
                        float r0 = v0 - __bfloat162float(b0), r1 = v1 - __bfloat162float(b1);
                        __nv_bfloat16 m0 = __float2bfloat16(r0), m1 = __float2bfloat16(r1);
                        long off = (long)row * ldN + gc;
                        *(uint32_t*)(o0 + off) = pack_bf2(b0, b1);
                        *(uint32_t*)(o1 + off) = pack_bf2(m0, m1);
                        if (T6) {
                            __nv_bfloat16 l0 = __float2bfloat16(r0 - __bfloat162float(m0));
                            __nv_bfloat16 l1 = __float2bfloat16(r1 - __bfloat162float(m1));
                            *(uint32_t*)(o2 + off) = pack_bf2(l0, l1);
                        }
                    }
                }
            } else if (EPI == 3) {
                if (act) {
                    int tok = tokens[row];
                    float wgt = wl[row];
                    float* orow = outF + (long)tok * 120;
#pragma unroll
                    for (int nt = 0; nt < NNT; nt++) {
                        int gc = colW + nt * 8 + (lane & 3) * 2;
                        if (gc < 120)     orow[gc]     += wgt * (acc[mt][nt][h8*2+0] + __ldg(&bias[gc]));
                        if (gc + 1 < 120) orow[gc + 1] += wgt * (acc[mt][nt][h8*2+1] + __ldg(&bias[gc+1]));
                    }
                }
            } else if (EPI == 1) {
                float lr[6] = {0.f, 0.f, 0.f, 0.f, 0.f, 0.f};
#pragma unroll
                for (int nt = 0; nt < NNT; nt++) {
#pragma unroll
                    for (int hh = 0; hh < 2; hh++) {
                        int gc = colW + nt * 8 + (lane & 3) * 2 + hh;
                        float h = gelu_exact(acc[mt][nt][h8 * 2 + hh] + __ldg(&bias[gc]));
#pragma unroll
                        for (int e = 0; e < 6; e++) lr[e] += h * sw[gc * 6 + e];
                    }
                }
#pragma unroll
                for (int e = 0; e < 6; e++) {
                    lr[e] += __shfl_xor_sync(0xffffffffu, lr[e], 1);
                    lr[e] += __shfl_xor_sync(0xffffffffu, lr[e], 2);
                }
                if ((lane & 3) == 0 && act)
#pragma unroll
                    for (int e = 0; e < 6; e++) atomicAdd(&lgsm[rl * 6 + e], lr[e]);
            } else if (EPI == 4) {
                float sacc = 0.f;
#pragma unroll
                for (int nt = 0; nt < NNT; nt++) {
#pragma unroll
                    for (int hh = 0; hh < 2; hh++) {
                        int gc = colW + nt * 8 + (lane & 3) * 2 + hh;
                        sacc += gelu_exact(acc[mt][nt][h8 * 2 + hh] + __ldg(&bias[gc])) * sw[gc];
                    }
                }
                sacc += __shfl_xor_sync(0xffffffffu, sacc, 1);
                sacc += __shfl_xor_sync(0xffffffffu, sacc, 2);
                if ((lane & 3) == 0 && act) atomicAdd(&lgsm[rl], sacc);
            }
        }
    }

    if (EPI == 1) {
        __syncthreads();
        int row = rowBase + t;
        bool act = (t < 128) && (row < Mrows);
        int i0 = 0, i1 = 1, pos0 = 0, pos1 = 0; float w0 = 0.f, w1 = 0.f;
        float lg[6];
        if (act) {
#pragma unroll
            for (int e = 0; e < 6; e++) lg[e] = lgsm[t * 6 + e] + b3[e];
            float mx = lg[0];
#pragma unroll
            for (int e = 1; e < 6; e++) mx = fmaxf(mx, lg[e]);
            float p[6], s = 0.f;
#pragma unroll
            for (int e = 0; e < 6; e++) { p[e] = expf(lg[e] - mx); s += p[e]; }
            float inv = 1.f / s;
            float* pr = outF + (long)row * 6;
#pragma unroll
            for (int e = 0; e < 6; e++) pr[e] = p[e] * inv;
            i0 = 0;
#pragma unroll
            for (int e = 1; e < 6; e++) if (lg[e] > lg[i0]) i0 = e;
            i1 = (i0 == 0) ? 1 : 0;
#pragma unroll
            for (int e = 0; e < 6; e++) if (e != i0 && lg[e] > lg[i1]) i1 = e;
            float rr = expf(lg[i1] - lg[i0]);
            w0 = 1.f / (1.f + rr); w1 = rr * w0;
            pos0 = atomicAdd(&bcnt[i0], 1);
            pos1 = atomicAdd(&bcnt[i1], 1);
        }
        __syncthreads();
        if (t < 6) bbase[t] = atomicAdd(&cnts[t], bcnt[t]);
        __syncthreads();
        if (act) {
            int s0 = bbase[i0] + pos0, s1 = bbase[i1] + pos1;
            lists[i0 * NTOK + s0] = row;  wlists[i0 * NTOK + s0] = w0;
            lists[i1 * NTOK + s1] = row;  wlists[i1 * NTOK + s1] = w1;
        }
    }
    if (EPI == 4) {
        __syncthreads();
        int row = rowBase + t;
        if (t < 128 && row < Mrows)
            outF[tokens[row]] += wl[row] * (lgsm[t] + b3[0]);
    }
}

// ---------------- aux loss (deterministic 2-stage tree reduction) ----------
__global__ __launch_bounds__(256) void aux_partial(const float* __restrict__ probs,
                                                   float* __restrict__ partials) {
    __shared__ float s[256][6];
    float acc[6] = {0.f, 0.f, 0.f, 0.f, 0.f, 0.f};
    int base = blockIdx.x * 384;
    for (int it = threadIdx.x; it < 384; it += 256) {
        const float* p = probs + (long)(base + it) * 6;
#pragma unroll
        for (int e = 0; e < 6; e++) acc[e] += p[e];
    }
#pragma unroll
    for (int e = 0; e < 6; e++) s[threadIdx.x][e] = acc[e];
    __syncthreads();
    for (int off = 128; off; off >>= 1) {
        if (threadIdx.x < off)
#pragma unroll
            for (int e = 0; e < 6; e++) s[threadIdx.x][e] += s[threadIdx.x + off][e];
        __syncthreads();
    }
    if (threadIdx.x < 6) partials[blockIdx.x * 6 + threadIdx.x] = s[0][threadIdx.x];
}

__global__ __launch_bounds__(256) void aux_final(const float* __restrict__ partials,
                                                 float* __restrict__ out_aux) {
    __shared__ float s[256][6];
#pragma unroll
    for (int e = 0; e < 6; e++) s[threadIdx.x][e] = partials[threadIdx.x * 6 + e];
    __syncthreads();
    for (int off = 128; off; off >>= 1) {
        if (threadIdx.x < off)
#pragma unroll
            for (int e = 0; e < 6; e++) s[threadIdx.x][e] += s[threadIdx.x + off][e];
        __syncthreads();
    }
    if (threadIdx.x == 0) {
        float aux = 0.f;
#pragma unroll
        for (int e = 0; e < 6; e++) {
            float avg = s[0][e] / (float)NTOK;
            aux += avg * avg;
        }
        out_aux[0] = 6.f * aux;
    }
}

// ---------------------------- host launcher --------------------------------
extern "C" void kernel_launch(void* const* d_in, const int* in_sizes, int n_in,
                              void* d_out, int out_size)
{
    const float* x   = (const float*)d_in[0];
    const float* rW1 = (const float*)d_in[1];  const float* rb1 = (const float*)d_in[2];
    const float* rW2 = (const float*)d_in[3];  const float* rb2 = (const float*)d_in[4];
    const float* rW3 = (const float*)d_in[5];  const float* rb3 = (const float*)d_in[6];
    const float* tW1 = (const float*)d_in[7];  const float* tb1 = (const float*)d_in[8];
    const float* tW2 = (const float*)d_in[9];  const float* tb2 = (const float*)d_in[10];
    const float* tW3 = (const float*)d_in[11]; const float* tb3 = (const float*)d_in[12];
    const float* sW1 = (const float*)d_in[13]; const float* sb1 = (const float*)d_in[14];
    const float* sW2 = (const float*)d_in[15]; const float* sb2 = (const float*)d_in[16];
    const float* sW3 = (const float*)d_in[17]; const float* sb3 = (const float*)d_in[18];
    float* out = (float*)d_out;

    __nv_bfloat16 *Xh,*Xm,*Xl,*H1h,*H1m,*H1l,*G1h,*G1l,*G2h,*G2l,*S1h,*S1l;
    __nv_bfloat16 *wr1h,*wr1m,*wr1l,*wr2h,*wr2m,*wr2l;
    __nv_bfloat16 *wt1h,*wt1l,*wt2h,*wt2l,*wt3h,*wt3l,*ws1h,*ws1l,*ws2h,*ws2l;
    int *list, *cnt; float *wlist, *partials;
    cudaGetSymbolAddress((void**)&Xh, g_Xh);   cudaGetSymbolAddress((void**)&Xm, g_Xm);
    cudaGetSymbolAddress((void**)&Xl, g_Xl);
    cudaGetSymbolAddress((void**)&H1h, g_H1h); cudaGetSymbolAddress((void**)&H1m, g_H1m);
    cudaGetSymbolAddress((void**)&H1l, g_H1l);
    cudaGetSymbolAddress((void**)&G1h, g_G1h); cudaGetSymbolAddress((void**)&G1l, g_G1l);
    cudaGetSymbolAddress((void**)&G2h, g_G2h); cudaGetSymbolAddress((void**)&G2l, g_G2l);
    cudaGetSymbolAddress((void**)&S1h, g_S1h); cudaGetSymbolAddress((void**)&S1l, g_S1l);
    cudaGetSymbolAddress((void**)&wr1h, g_wr1h); cudaGetSymbolAddress((void**)&wr1m, g_wr1m);
    cudaGetSymbolAddress((void**)&wr1l, g_wr1l);
    cudaGetSymbolAddress((void**)&wr2h, g_wr2h); cudaGetSymbolAddress((void**)&wr2m, g_wr2m);
    cudaGetSymbolAddress((void**)&wr2l, g_wr2l);
    cudaGetSymbolAddress((void**)&wt1h, g_wt1h); cudaGetSymbolAddress((void**)&wt1l, g_wt1l);
    cudaGetSymbolAddress((void**)&wt2h, g_wt2h); cudaGetSymbolAddress((void**)&wt2l, g_wt2l);
    cudaGetSymbolAddress((void**)&wt3h, g_wt3h); cudaGetSymbolAddress((void**)&wt3l, g_wt3l);
    cudaGetSymbolAddress((void**)&ws1h, g_ws1h); cudaGetSymbolAddress((void**)&ws1l, g_ws1l);
    cudaGetSymbolAddress((void**)&ws2h, g_ws2h); cudaGetSymbolAddress((void**)&ws2l, g_ws2l);
    cudaGetSymbolAddress((void**)&list, g_list); cudaGetSymbolAddress((void**)&wlist, g_wlist);
    cudaGetSymbolAddress((void**)&cnt, g_cnt);   cudaGetSymbolAddress((void**)&partials, g_partials);

    // dyn smem: 2 stages * NA*(16K + NTILE*128) + 6720 tail
    const int S3_128 = 2*3*(16384 + 128*128) + 6720;   // 203328
    const int S2_128 = 2*2*(16384 + 128*128) + 6720;   // 137792
    const int S2_64  = 2*2*(16384 + 64*128)  + 6720;   // 105024
    cudaFuncSetAttribute(gemmW<128,128,0,false,true>,  cudaFuncAttributeMaxDynamicSharedMemorySize, S3_128);
    cudaFuncSetAttribute(gemmW<128,256,1,false,true>,  cudaFuncAttributeMaxDynamicSharedMemorySize, S3_128);
    cudaFuncSetAttribute(gemmW<128,128,0,true,false>,  cudaFuncAttributeMaxDynamicSharedMemorySize, S2_128);
    cudaFuncSetAttribute(gemmW<128,256,0,false,false>, cudaFuncAttributeMaxDynamicSharedMemorySize, S2_128);
    cudaFuncSetAttribute(gemmW<128,256,3,false,false>, cudaFuncAttributeMaxDynamicSharedMemorySize, S2_128);
    cudaFuncSetAttribute(gemmW<64,128,4,false,false>,  cudaFuncAttributeMaxDynamicSharedMemorySize, S2_64);

    // 1. zero traj+scores + counters; split inputs; build weight images
    init_kernel<<<11616, 256>>>(out);
    convert_x<<<NTOK*128/256, 256>>>(x, Xh, Xm, Xl);
    convert_w<<<dim3(128,1,1), 256>>>(rW1, wr1h, wr1m, wr1l, 256, 256, 0, 0);
    convert_w<<<dim3(128,1,1), 256>>>(rW2, wr2h, wr2m, wr2l, 128, 128, 0, 0);
    convert_w<<<dim3(128,1,6), 256>>>(tW1, wt1h, wt1l, nullptr, 256, 256, 128L*256, 32768);
    convert_w<<<dim3(256,1,6), 256>>>(tW2, wt2h, wt2l, nullptr, 256, 256, 256L*256, 65536);
    convert_w<<<dim3(128,1,6), 256>>>(tW3, wt3h, wt3l, nullptr, 120, 128, 256L*120, 32768);
    convert_w<<<dim3(64,1,6),  256>>>(sW1, ws1h, ws1l, nullptr, 128, 128, 128L*128, 16384);
    convert_w<<<dim3(32,1,6),  256>>>(sW2, ws2h, ws2l, nullptr, 64,  64,  128L*64,  8192);

    const int GB = NTOK / 128;  // 768

    // 2. router (3-split / 6-term for selection accuracy)
    gemmW<128,128,0,false,true><<<dim3(GB,2),256,S3_128>>>(Xh,Xm,Xl, wr1h,wr1m,wr1l, rb1,
        nullptr,nullptr,nullptr, nullptr, NTOK, H1h,H1m,H1l, 256, 2048,
        nullptr, nullptr,nullptr,nullptr, nullptr,nullptr);
    gemmW<128,256,1,false,true><<<dim3(GB,1),256,S3_128>>>(H1h,H1m,H1l, wr2h,wr2m,wr2l, rb2,
        nullptr,nullptr,nullptr, nullptr, NTOK, nullptr,nullptr,nullptr, 128, 1024,
        out + PROBS_OFF, list, wlist, cnt, rW3, rb3);

    // 3. per-expert top-2 compute (dynamic counts read on device)
    for (int e = 0; e < EXP; e++) {
        const int* lst = list + e * NTOK;
        const float* wle = wlist + e * NTOK;
        const int* cp = cnt + e;
        gemmW<128,128,0,true,false><<<dim3(GB,2),256,S2_128>>>(Xh,Xm,nullptr,
            wt1h + e*32768L, wt1l + e*32768L, nullptr, tb1 + e*256,
            lst, nullptr, nullptr, cp, 0, G1h,G1l,nullptr, 256, 2048,
            nullptr, nullptr,nullptr,nullptr, nullptr,nullptr);
        gemmW<128,256,0,false,false><<<dim3(GB,2),256,S2_128>>>(G1h,G1l,nullptr,
            wt2h + e*65536L, wt2l + e*65536L, nullptr, tb2 + e*256,
            nullptr, nullptr, nullptr, cp, 0, G2h,G2l,nullptr, 256, 2048,
            nullptr, nullptr,nullptr,nullptr, nullptr,nullptr);
        gemmW<128,256,3,false,false><<<dim3(GB,1),256,S2_128>>>(G2h,G2l,nullptr,
            wt3h + e*32768L, wt3l + e*32768L, nullptr, tb3 + e*120,
            nullptr, lst, wle, cp, 0, nullptr,nullptr,nullptr, 120, 1024,
            out, nullptr,nullptr,nullptr, nullptr,nullptr);
        gemmW<128,128,0,true,false><<<dim3(GB,1),256,S2_128>>>(Xh,Xm,nullptr,
            ws1h + e*16384L, ws1l + e*16384L, nullptr, sb1 + e*128,
            lst, nullptr, nullptr, cp, 0, S1h,S1l,nullptr, 128, 1024,
            nullptr, nullptr,nullptr,nullptr, nullptr,nullptr);
        gemmW<64,128,4,false,false><<<dim3(GB,1),256,S2_64>>>(S1h,S1l,nullptr,
            ws2h + e*8192L, ws2l + e*8192L, nullptr, sb2 + e*64,
            nullptr, lst, wle, cp, 0, nullptr,nullptr,nullptr, 64, 512,
            out + SCORE_OFF, nullptr,nullptr,nullptr, sW3 + e*64, sb3 + e);
    }

    // 4. aux loss from probs
    aux_partial<<<256, 256>>>(out + PROBS_OFF, partials);
    aux_final<<<1, 256>>>(partials, out + AUX_OFF);
}

// round 7
// speedup vs baseline: 2.7381x; 1.2560x over previous
#include <cuda_runtime.h>
#include <cuda_bf16.h>
#include <cstdint>
#include <math.h>

#define NTOK 98304
#define EXP 6
#define TRAJ_LEN (NTOK*120)
#define SCORE_OFF TRAJ_LEN
#define AUX_OFF   (SCORE_OFF + NTOK)
#define PROBS_OFF (AUX_OFF + 1)

// ======================= helpers ===========================================
__device__ __forceinline__ uint32_t smem_u32(const void* p) {
    uint32_t a;
    asm("{ .reg .u64 t; cvta.to.shared.u64 t, %1; cvt.u32.u64 %0, t; }" : "=r"(a) : "l"(p));
    return a;
}
__device__ __forceinline__ uint32_t swz(uint32_t o) { return o ^ ((o >> 3) & 0x70); }

__device__ __forceinline__ void ldsm4(uint32_t* r, uint32_t addr) {
    asm volatile("ldmatrix.sync.aligned.m8n8.x4.shared.b16 {%0,%1,%2,%3}, [%4];"
        : "=r"(r[0]), "=r"(r[1]), "=r"(r[2]), "=r"(r[3]) : "r"(addr));
}
__device__ __forceinline__ void mma16816(float* d, const uint32_t* a, const uint32_t* b) {
    asm volatile("mma.sync.aligned.m16n8k16.row.col.f32.bf16.bf16.f32 "
        "{%0,%1,%2,%3}, {%4,%5,%6,%7}, {%8,%9}, {%0,%1,%2,%3};"
        : "+f"(d[0]), "+f"(d[1]), "+f"(d[2]), "+f"(d[3])
        : "r"(a[0]), "r"(a[1]), "r"(a[2]), "r"(a[3]), "r"(b[0]), "r"(b[1]));
}
#define CP_ASYNC16(dst, src, sz) \
    asm volatile("cp.async.cg.shared.global [%0], [%1], 16, %2;" \
        :: "r"(dst), "l"(src), "r"(sz))
#define CP_COMMIT() asm volatile("cp.async.commit_group;")
#define CP_WAIT1()  asm volatile("cp.async.wait_group 1;")
#define CP_WAIT0()  asm volatile("cp.async.wait_group 0;")

__device__ __forceinline__ float gelu_exact(float x) {
    return 0.5f * x * (1.0f + erff(x * 0.7071067811865476f));
}
__device__ __forceinline__ uint32_t pack_bf2(__nv_bfloat16 a, __nv_bfloat16 b) {
    return (uint32_t)__bfloat16_as_ushort(a) | ((uint32_t)__bfloat16_as_ushort(b) << 16);
}

// ======================= scratch (device globals) ===========================
#define NSLOT (2*NTOK)
__device__ __nv_bfloat16 g_Xh[NTOK*128],  g_Xm[NTOK*128],  g_Xl[NTOK*128];
__device__ __nv_bfloat16 g_H1h[NTOK*256], g_H1m[NTOK*256], g_H1l[NTOK*256];
__device__ __nv_bfloat16 g_G1h[NSLOT*256], g_G1l[NSLOT*256];
__device__ __nv_bfloat16 g_G2h[NSLOT*256], g_G2l[NSLOT*256];
__device__ __nv_bfloat16 g_S1h[NSLOT*128], g_S1l[NSLOT*128];
__device__ __nv_bfloat16 g_wr1h[32768],  g_wr1m[32768],  g_wr1l[32768];
__device__ __nv_bfloat16 g_wr2h[32768],  g_wr2m[32768],  g_wr2l[32768];
__device__ __nv_bfloat16 g_wt1h[196608], g_wt1l[196608];
__device__ __nv_bfloat16 g_wt2h[393216], g_wt2l[393216];
__device__ __nv_bfloat16 g_wt3h[196608], g_wt3l[196608];
__device__ __nv_bfloat16 g_ws1h[98304],  g_ws1l[98304];
__device__ __nv_bfloat16 g_ws2h[49152],  g_ws2l[49152];
__device__ int   g_list[EXP*NTOK];
__device__ float g_wlist[EXP*NTOK];
__device__ int   g_cnt[8];
__device__ int   g_off[8];
__device__ float g_partials[256*6];

// ======================= init + conversions ================================
__global__ void init_kernel(float* __restrict__ out) {
    long i = (long)blockIdx.x * blockDim.x + threadIdx.x;
    ((float4*)out)[i] = make_float4(0.f, 0.f, 0.f, 0.f);   // traj + scores
    if (blockIdx.x == 0 && threadIdx.x < 8) g_cnt[threadIdx.x] = 0;
}

__global__ void offsets_kernel() {
    if (threadIdx.x == 0) {
        int s = 0;
#pragma unroll
        for (int e = 0; e < EXP; e++) { g_off[e] = s; s += g_cnt[e]; }
    }
}

__global__ void convert_x(const float* __restrict__ x,
                          __nv_bfloat16* __restrict__ x0, __nv_bfloat16* __restrict__ x1,
                          __nv_bfloat16* __restrict__ x2) {
    long i = (long)blockIdx.x * 256 + threadIdx.x;
    float v = x[i];
    __nv_bfloat16 h = __float2bfloat16(v);
    float r = v - __bfloat162float(h);
    __nv_bfloat16 m = __float2bfloat16(r);
    x0[i] = h; x1[i] = m;
    x2[i] = __float2bfloat16(r - __bfloat162float(m));
}

// W [K,Nin] f32 row-major (expert stride) -> SW128-swizzled bf16 images.
__global__ void convert_w(const float* __restrict__ W,
                          __nv_bfloat16* __restrict__ o0, __nv_bfloat16* __restrict__ o1,
                          __nv_bfloat16* __restrict__ o2,
                          int Nin, int Npad, long wstride, long ostride) {
    int e = blockIdx.z;
    int idx = blockIdx.x * 256 + threadIdx.x;
    int ce = Npad * 64;
    int c = idx / ce, rem = idx - c * ce;
    int n = rem >> 6, kk = rem & 63;
    float v = (n < Nin) ? W[(long)e * wstride + (long)(c * 64 + kk) * Nin + n] : 0.f;
    __nv_bfloat16 h = __float2bfloat16(v);
    float r = v - __bfloat162float(h);
    __nv_bfloat16 m = __float2bfloat16(r);
    uint32_t bo = (uint32_t)(n >> 3) * 1024u + (uint32_t)(n & 7) * 128u + (uint32_t)kk * 2u;
    bo = swz(bo);
    long o = (long)e * ostride + (long)c * ce + (bo >> 1);
    o0[o] = h; o1[o] = m;
    if (o2) o2[o] = __float2bfloat16(r - __bfloat162float(m));
}

// ======================= pipelined mma.sync split-bf16 GEMM =================
// CTA: 128 rows x NTILE cols (grid.y slices NTILE-col blocks of N).
// blockIdx.z = expert (weights/bias/lists strided, scratch rows offset by g_off[e]).
// k chunks of 64, 2-stage cp.async double buffer. 8 warps 4(M)x2(N).
// EPI 0: bias+GELU -> split-bf16 store      EPI 1: router tail
// EPI 3: traj atomic scatter                EPI 4: score fused dot + atomic
template<int NTILE, int K, int EPI, bool GATHER, bool T6>
__global__ void __launch_bounds__(256)
gemmW(const __nv_bfloat16* __restrict__ A0b, const __nv_bfloat16* __restrict__ A1b,
      const __nv_bfloat16* __restrict__ A2b,
      const __nv_bfloat16* __restrict__ B0b, const __nv_bfloat16* __restrict__ B1b,
      const __nv_bfloat16* __restrict__ B2b, long bStrideE,
      const float* __restrict__ biasB, long biasStrideE,
      const int* __restrict__ listsB, const float* __restrict__ wlB,
      const int* __restrict__ cntArr, int Mfixed,
      const int* __restrict__ offs,
      __nv_bfloat16* __restrict__ o0, __nv_bfloat16* __restrict__ o1,
      __nv_bfloat16* __restrict__ o2,
      int ldN, int npad4,
      float* __restrict__ outF,
      int* __restrict__ listsOut, float* __restrict__ wlistsOut, int* __restrict__ cntsOut,
      const float* __restrict__ w3B, long w3StrideE,
      const float* __restrict__ b3B, int b3Stride)
{
    constexpr int NA = T6 ? 3 : 2;
    constexpr int NT = T6 ? 6 : 3;
    constexpr int NC = K / 64;
    constexpr int NNT = NTILE / 16;
    constexpr int NG  = NNT / 2;
    constexpr int ABYTES = 16384;
    constexpr int BBYTES = NTILE * 128;
    constexpr int STAGE  = NA * (ABYTES + BBYTES);
    constexpr int EXTRA  = 2 * STAGE;
    constexpr int NB4 = NTILE * 8;

    extern __shared__ char smem[];
    const int e = blockIdx.z;
    int Mrows = cntArr ? cntArr[e] : Mfixed;
    int rowBase = blockIdx.x << 7;
    if (rowBase >= Mrows) return;
    const int roff = offs ? offs[e] : 0;
    const float* bias = biasB + (long)e * biasStrideE;
    const int* gather = listsB ? (listsB + (long)e * NTOK) : nullptr;
    const float* wl = wlB ? (wlB + (long)e * NTOK) : nullptr;
    const float* w3 = w3B ? (w3B + (long)e * w3StrideE) : nullptr;
    const float* b3 = b3B ? (b3B + (long)e * b3Stride) : nullptr;

    const int t = threadIdx.x, lane = t & 31, w = t >> 5;
    const int wm = w & 3, wn = w >> 2;
    uint32_t sb = smem_u32(smem);
    int*   sgat = (int*)(smem + EXTRA);
    float* sw   = (float*)(smem + EXTRA + 512);
    float* lgsm = (float*)(smem + EXTRA + 512 + 3072);
    int*   bcnt = (int*)(smem + EXTRA + 512 + 3072 + 3072);
    int*   bbase = bcnt + 8;

    if (GATHER && t < 128) { int gr = rowBase + t; sgat[t] = (gr < Mrows) ? gather[gr] : 0; }
    if (EPI == 1) {
        for (int i = t; i < 768; i += 256) { sw[i] = w3[i]; lgsm[i] = 0.f; }
        if (t < 8) bcnt[t] = 0;
    }
    if (EPI == 4) { if (t < 64) sw[t] = w3[t]; if (t < 128) lgsm[t] = 0.f; }
    __syncthreads();

    const __nv_bfloat16* Asp[3] = {A0b, A1b, A2b};
    const uint4* Bsp[3] = {
        (const uint4*)(B0b + (long)e * bStrideE),
        (const uint4*)(B1b + (long)e * bStrideE),
        T6 ? (const uint4*)(B2b + (long)e * bStrideE) : nullptr};
    const int ny4 = blockIdx.y * (NTILE * 8);

    uint32_t aoff[2];
#pragma unroll
    for (int mt = 0; mt < 2; mt++) {
        int r = wm * 32 + mt * 16 + (lane & 15);
        aoff[mt] = (uint32_t)((r >> 3) * 1024 + (r & 7) * 128) + (uint32_t)((lane >> 4) * 16);
    }
    uint32_t boff[NG];
#pragma unroll
    for (int g = 0; g < NG; g++) {
        int r = wn * (NTILE / 2) + g * 16 + ((lane >> 4) & 1) * 8 + (lane & 7);
        boff[g] = (uint32_t)((r >> 3) * 1024 + (r & 7) * 128) + (uint32_t)(((lane >> 3) & 1) * 16);
    }

    auto stage = [&](int c, int s) {
        uint32_t base = sb + s * STAGE;
#pragma unroll
        for (int a = 0; a < NA; a++) {
            const __nv_bfloat16* Ab = Asp[a];
#pragma unroll
            for (int rep = 0; rep < 4; rep++) {
                int i = t + rep * 256;
                int row = i >> 3, seg = i & 7;
                int gr = rowBase + row;
                int val = (gr < Mrows) ? 16 : 0;
                long ar = GATHER ? (long)sgat[row]
                                 : (long)roff + (gr < Mrows ? gr : 0);
                const void* src = Ab + ar * (long)K + c * 64 + seg * 8;
                uint32_t dst = base + a * ABYTES +
                    swz((uint32_t)((row >> 3) * 1024 + (row & 7) * 128 + seg * 16));
                CP_ASYNC16(dst, src, val);
            }
        }
#pragma unroll
        for (int a = 0; a < NA; a++) {
            const uint4* src0 = Bsp[a] + (long)c * npad4 + ny4;
#pragma unroll
            for (int rep = 0; rep < NB4 / 256; rep++) {
                int i = t + rep * 256;
                CP_ASYNC16(base + NA * ABYTES + a * BBYTES + (uint32_t)i * 16, src0 + i, 16);
            }
        }
        CP_COMMIT();
    };

    float acc[2][NNT][4];
#pragma unroll
    for (int mt = 0; mt < 2; mt++)
#pragma unroll
        for (int nt = 0; nt < NNT; nt++)
#pragma unroll
            for (int q = 0; q < 4; q++) acc[mt][nt][q] = 0.f;

    stage(0, 0);
    for (int c = 0; c < NC; c++) {
        int s = c & 1;
        if (c + 1 < NC) { stage(c + 1, (c + 1) & 1); CP_WAIT1(); }
        else            { CP_WAIT0(); }
        __syncthreads();
        uint32_t base = sb + s * STAGE;
        const int TI[6] = {0, 0, 1, 1, 0, 2}, TJ[6] = {0, 1, 0, 1, 2, 0};
#pragma unroll
        for (int ks = 0; ks < 4; ks++) {
            uint32_t af[NA][2][4];
#pragma unroll
            for (int a = 0; a < NA; a++)
#pragma unroll
                for (int mt = 0; mt < 2; mt++)
                    ldsm4(af[a][mt], base + a * ABYTES + swz(aoff[mt] + (uint32_t)ks * 32));
#pragma unroll
            for (int g = 0; g < NG; g++) {
                uint32_t bf[NA][4];
#pragma unroll
                for (int a = 0; a < NA; a++)
                    ldsm4(bf[a], base + NA * ABYTES + a * BBYTES + swz(boff[g] + (uint32_t)ks * 32));
#pragma unroll
                for (int tt = 0; tt < NT; tt++)
#pragma unroll
                    for (int mt = 0; mt < 2; mt++)
#pragma unroll
                        for (int hn = 0; hn < 2; hn++)
                            mma16816(acc[mt][g * 2 + hn], af[TI[tt]][mt], &bf[TJ[tt]][hn * 2]);
            }
        }
        __syncthreads();
    }

    // ----------------------- epilogue (from fragments) ---------------------
    const int colW = wn * (NTILE / 2);
    const int colBase = blockIdx.y * NTILE;
#pragma unroll
    for (int mt = 0; mt < 2; mt++) {
#pragma unroll
        for (int h8 = 0; h8 < 2; h8++) {
            int rl = wm * 32 + mt * 16 + (lane >> 2) + h8 * 8;
            int row = rowBase + rl;
            bool act = row < Mrows;
            if (EPI == 0) {
                if (act) {
#pragma unroll
                    for (int nt = 0; nt < NNT; nt++) {
                        int gc = colBase + colW + nt * 8 + (lane & 3) * 2;
                        float v0 = gelu_exact(acc[mt][nt][h8 * 2 + 0] + __ldg(&bias[gc]));
                        float v1 = gelu_exact(acc[mt][nt][h8 * 2 + 1] + __ldg(&bias[gc + 1]));
                        __nv_bfloat16 b0 = __float2bfloat16(v0), b1 = __float2bfloat16(v1);
                        float r0 = v0 - __bfloat162float(b0), r1 = v1 - __bfloat162float(b1);
                        __nv_bfloat16 m0 = __float2bfloat16(r0), m1 = __float2bfloat16(r1);
                        long off = (long)(roff + row) * ldN + gc;
                        *(uint32_t*)(o0 + off) = pack_bf2(b0, b1);
                        *(uint32_t*)(o1 + off) = pack_bf2(m0, m1);
                        if (T6) {
                            __nv_bfloat16 l0 = __float2bfloat16(r0 - __bfloat162float(m0));
                            __nv_bfloat16 l1 = __float2bfloat16(r1 - __bfloat162float(m1));
                            *(uint32_t*)(o2 + off) = pack_bf2(l0, l1);
                        }
                    }
                }
            } else if (EPI == 3) {
                if (act) {
                    int tok = gather[row];
                    float wgt = wl[row];
                    float* orow = outF + (long)tok * 120;
#pragma unroll
                    for (int nt = 0; nt < NNT; nt++) {
                        int gc = colBase + colW + nt * 8 + (lane & 3) * 2;
                        if (gc < 120)
                            atomicAdd(&orow[gc], wgt * (acc[mt][nt][h8*2+0] + __ldg(&bias[gc])));
                        if (gc + 1 < 120)
                            atomicAdd(&orow[gc + 1], wgt * (acc[mt][nt][h8*2+1] + __ldg(&bias[gc+1])));
                    }
                }
            } else if (EPI == 1) {
                float lr[6] = {0.f, 0.f, 0.f, 0.f, 0.f, 0.f};
#pragma unroll
                for (int nt = 0; nt < NNT; nt++) {
#pragma unroll
                    for (int hh = 0; hh < 2; hh++) {
                        int gc = colW + nt * 8 + (lane & 3) * 2 + hh;
                        float h = gelu_exact(acc[mt][nt][h8 * 2 + hh] + __ldg(&bias[gc]));
#pragma unroll
                        for (int ee = 0; ee < 6; ee++) lr[ee] += h * sw[gc * 6 + ee];
                    }
                }
#pragma unroll
                for (int ee = 0; ee < 6; ee++) {
                    lr[ee] += __shfl_xor_sync(0xffffffffu, lr[ee], 1);
                    lr[ee] += __shfl_xor_sync(0xffffffffu, lr[ee], 2);
                }
                if ((lane & 3) == 0 && act)
#pragma unroll
                    for (int ee = 0; ee < 6; ee++) atomicAdd(&lgsm[rl * 6 + ee], lr[ee]);
            } else if (EPI == 4) {
                float sacc = 0.f;
#pragma unroll
                for (int nt = 0; nt < NNT; nt++) {
#pragma unroll
                    for (int hh = 0; hh < 2; hh++) {
                        int gc = colW + nt * 8 + (lane & 3) * 2 + hh;
                        sacc += gelu_exact(acc[mt][nt][h8 * 2 + hh] + __ldg(&bias[gc])) * sw[gc];
                    }
                }
                sacc += __shfl_xor_sync(0xffffffffu, sacc, 1);
                sacc += __shfl_xor_sync(0xffffffffu, sacc, 2);
                if ((lane & 3) == 0 && act) atomicAdd(&lgsm[rl], sacc);
            }
        }
    }

    if (EPI == 1) {
        __syncthreads();
        int row = rowBase + t;
        bool act = (t < 128) && (row < Mrows);
        int i0 = 0, i1 = 1, pos0 = 0, pos1 = 0; float w0 = 0.f, w1 = 0.f;
        float lg[6];
        if (act) {
#pragma unroll
            for (int ee = 0; ee < 6; ee++) lg[ee] = lgsm[t * 6 + ee] + b3[ee];
            float mx = lg[0];
#pragma unroll
            for (int ee = 1; ee < 6; ee++) mx = fmaxf(mx, lg[ee]);
            float p[6], s = 0.f;
#pragma unroll
            for (int ee = 0; ee < 6; ee++) { p[ee] = expf(lg[ee] - mx); s += p[ee]; }
            float inv = 1.f / s;
            float* pr = outF + (long)row * 6;
#pragma unroll
            for (int ee = 0; ee < 6; ee++) pr[ee] = p[ee] * inv;
            i0 = 0;
#pragma unroll
            for (int ee = 1; ee < 6; ee++) if (lg[ee] > lg[i0]) i0 = ee;
            i1 = (i0 == 0) ? 1 : 0;
#pragma unroll
            for (int ee = 0; ee < 6; ee++) if (ee != i0 && lg[ee] > lg[i1]) i1 = ee;
            float rr = expf(lg[i1] - lg[i0]);
            w0 = 1.f / (1.f + rr); w1 = rr * w0;
            pos0 = atomicAdd(&bcnt[i0], 1);
            pos1 = atomicAdd(&bcnt[i1], 1);
        }
        __syncthreads();
        if (t < 6) bbase[t] = atomicAdd(&cntsOut[t], bcnt[t]);
        __syncthreads();
        if (act) {
            int s0 = bbase[i0] + pos0, s1 = bbase[i1] + pos1;
            listsOut[i0 * NTOK + s0] = row;  wlistsOut[i0 * NTOK + s0] = w0;
            listsOut[i1 * NTOK + s1] = row;  wlistsOut[i1 * NTOK + s1] = w1;
        }
    }
    if (EPI == 4) {
        __syncthreads();
        int row = rowBase + t;
        if (t < 128 && row < Mrows)
            atomicAdd(&outF[gather[row]], wl[row] * (lgsm[t] + b3[0]));
    }
}

// ---------------- aux loss (deterministic 2-stage tree reduction) ----------
__global__ __launch_bounds__(256) void aux_partial(const float* __restrict__ probs,
                                                   float* __restrict__ partials) {
    __shared__ float s[256][6];
    float acc[6] = {0.f, 0.f, 0.f, 0.f, 0.f, 0.f};
    int base = blockIdx.x * 384;
    for (int it = threadIdx.x; it < 384; it += 256) {
        const float* p = probs + (long)(base + it) * 6;
#pragma unroll
        for (int e = 0; e < 6; e++) acc[e] += p[e];
    }
#pragma unroll
    for (int e = 0; e < 6; e++) s[threadIdx.x][e] = acc[e];
    __syncthreads();
    for (int off = 128; off; off >>= 1) {
        if (threadIdx.x < off)
#pragma unroll
            for (int e = 0; e < 6; e++) s[threadIdx.x][e] += s[threadIdx.x + off][e];
        __syncthreads();
    }
    if (threadIdx.x < 6) partials[blockIdx.x * 6 + threadIdx.x] = s[0][threadIdx.x];
}

__global__ __launch_bounds__(256) void aux_final(const float* __restrict__ partials,
                                                 float* __restrict__ out_aux) {
    __shared__ float s[256][6];
#pragma unroll
    for (int e = 0; e < 6; e++) s[threadIdx.x][e] = partials[threadIdx.x * 6 + e];
    __syncthreads();
    for (int off = 128; off; off >>= 1) {
        if (threadIdx.x < off)
#pragma unroll
            for (int e = 0; e < 6; e++) s[threadIdx.x][e] += s[threadIdx.x + off][e];
        __syncthreads();
    }
    if (threadIdx.x == 0) {
        float aux = 0.f;
#pragma unroll
        for (int e = 0; e < 6; e++) {
            float avg = s[0][e] / (float)NTOK;
            aux += avg * avg;
        }
        out_aux[0] = 6.f * aux;
    }
}

// ---------------------------- host launcher --------------------------------
extern "C" void kernel_launch(void* const* d_in, const int* in_sizes, int n_in,
                              void* d_out, int out_size)
{
    const float* x   = (const float*)d_in[0];
    const float* rW1 = (const float*)d_in[1];  const float* rb1 = (const float*)d_in[2];
    const float* rW2 = (const float*)d_in[3];  const float* rb2 = (const float*)d_in[4];
    const float* rW3 = (const float*)d_in[5];  const float* rb3 = (const float*)d_in[6];
    const float* tW1 = (const float*)d_in[7];  const float* tb1 = (const float*)d_in[8];
    const float* tW2 = (const float*)d_in[9];  const float* tb2 = (const float*)d_in[10];
    const float* tW3 = (const float*)d_in[11]; const float* tb3 = (const float*)d_in[12];
    const float* sW1 = (const float*)d_in[13]; const float* sb1 = (const float*)d_in[14];
    const float* sW2 = (const float*)d_in[15]; const float* sb2 = (const float*)d_in[16];
    const float* sW3 = (const float*)d_in[17]; const float* sb3 = (const float*)d_in[18];
    float* out = (float*)d_out;

    __nv_bfloat16 *Xh,*Xm,*Xl,*H1h,*H1m,*H1l,*G1h,*G1l,*G2h,*G2l,*S1h,*S1l;
    __nv_bfloat16 *wr1h,*wr1m,*wr1l,*wr2h,*wr2m,*wr2l;
    __nv_bfloat16 *wt1h,*wt1l,*wt2h,*wt2l,*wt3h,*wt3l,*ws1h,*ws1l,*ws2h,*ws2l;
    int *list, *cnt, *offs; float *wlist, *partials;
    cudaGetSymbolAddress((void**)&Xh, g_Xh);   cudaGetSymbolAddress((void**)&Xm, g_Xm);
    cudaGetSymbolAddress((void**)&Xl, g_Xl);
    cudaGetSymbolAddress((void**)&H1h, g_H1h); cudaGetSymbolAddress((void**)&H1m, g_H1m);
    cudaGetSymbolAddress((void**)&H1l, g_H1l);
    cudaGetSymbolAddress((void**)&G1h, g_G1h); cudaGetSymbolAddress((void**)&G1l, g_G1l);
    cudaGetSymbolAddress((void**)&G2h, g_G2h); cudaGetSymbolAddress((void**)&G2l, g_G2l);
    cudaGetSymbolAddress((void**)&S1h, g_S1h); cudaGetSymbolAddress((void**)&S1l, g_S1l);
    cudaGetSymbolAddress((void**)&wr1h, g_wr1h); cudaGetSymbolAddress((void**)&wr1m, g_wr1m);
    cudaGetSymbolAddress((void**)&wr1l, g_wr1l);
    cudaGetSymbolAddress((void**)&wr2h, g_wr2h); cudaGetSymbolAddress((void**)&wr2m, g_wr2m);
    cudaGetSymbolAddress((void**)&wr2l, g_wr2l);
    cudaGetSymbolAddress((void**)&wt1h, g_wt1h); cudaGetSymbolAddress((void**)&wt1l, g_wt1l);
    cudaGetSymbolAddress((void**)&wt2h, g_wt2h); cudaGetSymbolAddress((void**)&wt2l, g_wt2l);
    cudaGetSymbolAddress((void**)&wt3h, g_wt3h); cudaGetSymbolAddress((void**)&wt3l, g_wt3l);
    cudaGetSymbolAddress((void**)&ws1h, g_ws1h); cudaGetSymbolAddress((void**)&ws1l, g_ws1l);
    cudaGetSymbolAddress((void**)&ws2h, g_ws2h); cudaGetSymbolAddress((void**)&ws2l, g_ws2l);
    cudaGetSymbolAddress((void**)&list, g_list); cudaGetSymbolAddress((void**)&wlist, g_wlist);
    cudaGetSymbolAddress((void**)&cnt, g_cnt);   cudaGetSymbolAddress((void**)&offs, g_off);
    cudaGetSymbolAddress((void**)&partials, g_partials);

    const int S3_128 = 2*3*(16384 + 128*128) + 6720;   // 203328 (router)
    const int S2_64  = 2*2*(16384 + 64*128)  + 6720;   // 105024 (experts, 2 CTA/SM)
    cudaFuncSetAttribute(gemmW<128,128,0,false,true>,  cudaFuncAttributeMaxDynamicSharedMemorySize, S3_128);
    cudaFuncSetAttribute(gemmW<128,256,1,false,true>,  cudaFuncAttributeMaxDynamicSharedMemorySize, S3_128);
    cudaFuncSetAttribute(gemmW<64,128,0,true,false>,   cudaFuncAttributeMaxDynamicSharedMemorySize, S2_64);
    cudaFuncSetAttribute(gemmW<64,256,0,false,false>,  cudaFuncAttributeMaxDynamicSharedMemorySize, S2_64);
    cudaFuncSetAttribute(gemmW<64,256,3,false,false>,  cudaFuncAttributeMaxDynamicSharedMemorySize, S2_64);
    cudaFuncSetAttribute(gemmW<64,128,4,false,false>,  cudaFuncAttributeMaxDynamicSharedMemorySize, S2_64);

    // 1. zero traj+scores + counters; split inputs; build weight images
    init_kernel<<<11616, 256>>>(out);
    convert_x<<<NTOK*128/256, 256>>>(x, Xh, Xm, Xl);
    convert_w<<<dim3(128,1,1), 256>>>(rW1, wr1h, wr1m, wr1l, 256, 256, 0, 0);
    convert_w<<<dim3(128,1,1), 256>>>(rW2, wr2h, wr2m, wr2l, 128, 128, 0, 0);
    convert_w<<<dim3(128,1,6), 256>>>(tW1, wt1h, wt1l, nullptr, 256, 256, 128L*256, 32768);
    convert_w<<<dim3(256,1,6), 256>>>(tW2, wt2h, wt2l, nullptr, 256, 256, 256L*256, 65536);
    convert_w<<<dim3(128,1,6), 256>>>(tW3, wt3h, wt3l, nullptr, 120, 128, 256L*120, 32768);
    convert_w<<<dim3(64,1,6),  256>>>(sW1, ws1h, ws1l, nullptr, 128, 128, 128L*128, 16384);
    convert_w<<<dim3(32,1,6),  256>>>(sW2, ws2h, ws2l, nullptr, 64,  64,  128L*64,  8192);

    const int GB = NTOK / 128;  // 768

    // 2. router (3-split / 6-term for selection accuracy)
    gemmW<128,128,0,false,true><<<dim3(GB,2,1),256,S3_128>>>(Xh,Xm,Xl,
        wr1h,wr1m,wr1l, 0, rb1, 0,
        nullptr, nullptr, nullptr, NTOK, nullptr,
        H1h,H1m,H1l, 256, 2048,
        nullptr, nullptr,nullptr,nullptr, nullptr,0, nullptr,0);
    gemmW<128,256,1,false,true><<<dim3(GB,1,1),256,S3_128>>>(H1h,H1m,H1l,
        wr2h,wr2m,wr2l, 0, rb2, 0,
        nullptr, nullptr, nullptr, NTOK, nullptr,
        nullptr,nullptr,nullptr, 128, 1024,
        out + PROBS_OFF, list, wlist, cnt, rW3, 0, rb3, 0);
    offsets_kernel<<<1, 32>>>();

    // 3. merged expert stages (blockIdx.z = expert)
    gemmW<64,128,0,true,false><<<dim3(GB,4,EXP),256,S2_64>>>(Xh,Xm,nullptr,
        wt1h, wt1l, nullptr, 32768, tb1, 256,
        list, nullptr, cnt, 0, offs,
        G1h,G1l,nullptr, 256, 2048,
        nullptr, nullptr,nullptr,nullptr, nullptr,0, nullptr,0);
    gemmW<64,128,0,true,false><<<dim3(GB,2,EXP),256,S2_64>>>(Xh,Xm,nullptr,
        ws1h, ws1l, nullptr, 16384, sb1, 128,
        list, nullptr, cnt, 0, offs,
        S1h,S1l,nullptr, 128, 1024,
        nullptr, nullptr,nullptr,nullptr, nullptr,0, nullptr,0);
    gemmW<64,256,0,false,false><<<dim3(GB,4,EXP),256,S2_64>>>(G1h,G1l,nullptr,
        wt2h, wt2l, nullptr, 65536, tb2, 256,
        nullptr, nullptr, cnt, 0, offs,
        G2h,G2l,nullptr, 256, 2048,
        nullptr, nullptr,nullptr,nullptr, nullptr,0, nullptr,0);
    gemmW<64,256,3,false,false><<<dim3(GB,2,EXP),256,S2_64>>>(G2h,G2l,nullptr,
        wt3h, wt3l, nullptr, 32768, tb3, 120,
        list, wlist, cnt, 0, offs,
        nullptr,nullptr,nullptr, 120, 1024,
        out, nullptr,nullptr,nullptr, nullptr,0, nullptr,0);
    gemmW<64,128,4,false,false><<<dim3(GB,1,EXP),256,S2_64>>>(S1h,S1l,nullptr,
        ws2h, ws2l, nullptr, 8192, sb2, 64,
        list, wlist, cnt, 0, offs,
        nullptr,nullptr,nullptr, 64, 512,
        out + SCORE_OFF, nullptr,nullptr,nullptr, sW3, 64, sb3, 1);

    // 4. aux loss from probs
    aux_partial<<<256, 256>>>(out + PROBS_OFF, partials);
    aux_final<<<1, 256>>>(partials, out + AUX_OFF);
}